// round 13
// baseline (speedup 1.0000x reference)
#include <cuda_runtime.h>
#include <cuda_bf16.h>
#include <cstdint>

#define NUM_CLASSES 1000
#define FEAT_DIM    512
#define F4_PER_ROW  (FEAT_DIM / 4)     // 128
#define BATCH       32768
#define CHUNK       4                  // sorted rows per warp
// ALPHA = 0.5

// Scratch (device globals, allocation-free). Zero at module load; restored to
// zero by the kernels themselves each call => deterministic across replays.
__device__ __align__(16) float g_sums[NUM_CLASSES * FEAT_DIM];
__device__ int   g_hist[NUM_CLASSES];
__device__ int   g_offsets[NUM_CLASSES];
__device__ int   g_cursor[NUM_CLASSES];
__device__ int   g_rowidx[BATCH];
__device__ int   g_sortedlab[BATCH];
__device__ float g_loss;

// ---------------------------------------------------------------------------
// 1) Histogram of labels (smem-aggregated, merged to global).
// ---------------------------------------------------------------------------
__global__ void __launch_bounds__(1024) hist_kernel(const int* __restrict__ labels)
{
    __shared__ int sh[NUM_CLASSES];
    for (int i = threadIdx.x; i < NUM_CLASSES; i += 1024) sh[i] = 0;
    __syncthreads();

    const int stride = gridDim.x * 1024;
    for (int r = blockIdx.x * 1024 + threadIdx.x; r < BATCH; r += stride)
        atomicAdd(&sh[labels[r]], 1);
    __syncthreads();

    for (int i = threadIdx.x; i < NUM_CLASSES; i += 1024) {
        int v = sh[i];
        if (v) atomicAdd(&g_hist[i], v);
    }
}

// ---------------------------------------------------------------------------
// 2) Exclusive prefix sum over 1000 counts (single block, Hillis-Steele).
// ---------------------------------------------------------------------------
__global__ void __launch_bounds__(1024) scan_kernel()
{
    __shared__ int sh[1024];
    const int t = threadIdx.x;
    sh[t] = (t < NUM_CLASSES) ? g_hist[t] : 0;
    __syncthreads();

    #pragma unroll
    for (int off = 1; off < 1024; off <<= 1) {
        int v = (t >= off) ? sh[t - off] : 0;
        __syncthreads();
        sh[t] += v;
        __syncthreads();
    }
    if (t < NUM_CLASSES) {
        int excl = sh[t] - g_hist[t];
        g_offsets[t] = excl;
        g_cursor[t]  = excl;
    }
}

// ---------------------------------------------------------------------------
// 3) Scatter row indices (and their labels) into class-sorted order.
// ---------------------------------------------------------------------------
__global__ void __launch_bounds__(1024) scatter_kernel(const int* __restrict__ labels)
{
    const int stride = gridDim.x * 1024;
    for (int r = blockIdx.x * 1024 + threadIdx.x; r < BATCH; r += stride) {
        const int lab = labels[r];
        int pos = atomicAdd(&g_cursor[lab], 1);
        g_rowidx[pos] = r;
        g_sortedlab[pos] = lab;
    }
}

// ---------------------------------------------------------------------------
// 4) Main: one warp per CHUNK consecutive rows of the SORTED order.
//    Rows in a chunk almost always share a class -> accumulate in registers,
//    REDG-flush once per distinct label (~1.1x per chunk instead of 4x).
//    Also accumulates sum(f^2) for the loss expansion:
//      sum ||f - c[lab]||^2 = sum f^2 - 2 sum_c <s_c,c_c> + sum_c cnt_c ||c_c||^2
// ---------------------------------------------------------------------------
__device__ __forceinline__ void flush_acc(float4* acc, int lab, int lane)
{
    float* s = g_sums + (size_t)lab * FEAT_DIM;
    #pragma unroll
    for (int i = 0; i < 4; i++) {
        const int idx = lane + i * 32;
        asm volatile("red.global.add.v4.f32 [%0], {%1, %2, %3, %4};"
                     :: "l"(s + idx * 4),
                        "f"(acc[i].x), "f"(acc[i].y), "f"(acc[i].z), "f"(acc[i].w)
                     : "memory");
    }
}

__global__ void __launch_bounds__(256) center_main_kernel(
    const float* __restrict__ features)
{
    const int tid  = blockIdx.x * blockDim.x + threadIdx.x;
    const int warp = tid >> 5;          // 0 .. BATCH/CHUNK-1 (grid sized exactly)
    const int lane = threadIdx.x & 31;
    const int base = warp * CHUNK;

    const float4* __restrict__ F = reinterpret_cast<const float4*>(features);

    // chunk metadata (uniform loads -> broadcast)
    int rows[CHUNK], labs[CHUNK];
    #pragma unroll
    for (int j = 0; j < CHUNK; j++) {
        rows[j] = g_rowidx[base + j];
        labs[j] = g_sortedlab[base + j];
    }

    float sumsq = 0.0f;
    float4 acc[4];
    int cur = labs[0];

    // row 0 initializes the accumulator
    {
        const size_t ro = (size_t)rows[0] * F4_PER_ROW;
        #pragma unroll
        for (int i = 0; i < 4; i++) {
            float4 v = F[ro + lane + i * 32];
            acc[i] = v;
            sumsq += v.x * v.x + v.y * v.y + v.z * v.z + v.w * v.w;
        }
    }

    #pragma unroll
    for (int j = 1; j < CHUNK; j++) {
        const size_t ro = (size_t)rows[j] * F4_PER_ROW;
        float4 v[4];
        #pragma unroll
        for (int i = 0; i < 4; i++) v[i] = F[ro + lane + i * 32];

        if (labs[j] != cur) {               // rare (~12% of chunks)
            flush_acc(acc, cur, lane);
            cur = labs[j];
            #pragma unroll
            for (int i = 0; i < 4; i++) acc[i] = v[i];
        } else {
            #pragma unroll
            for (int i = 0; i < 4; i++) {
                acc[i].x += v[i].x; acc[i].y += v[i].y;
                acc[i].z += v[i].z; acc[i].w += v[i].w;
            }
        }
        #pragma unroll
        for (int i = 0; i < 4; i++)
            sumsq += v[i].x * v[i].x + v[i].y * v[i].y
                   + v[i].z * v[i].z + v[i].w * v[i].w;
    }
    flush_acc(acc, cur, lane);

    // ---- block-reduce sum(f^2) -> one atomic per block ----
    #pragma unroll
    for (int off = 16; off > 0; off >>= 1)
        sumsq += __shfl_xor_sync(0xffffffffu, sumsq, off);

    __shared__ float s_ws[8];
    const int wib = threadIdx.x >> 5;
    if (lane == 0) s_ws[wib] = sumsq;
    __syncthreads();
    if (threadIdx.x == 0) {
        float bs = 0.0f;
        #pragma unroll
        for (int w = 0; w < 8; w++) bs += s_ws[w];
        atomicAdd(&g_loss, bs);
    }
}

// ---------------------------------------------------------------------------
// 5) Finalize: flat, one float4 element per thread (128000 threads).
//    Center update + loss cross/quadratic terms + g_sums self-reset.
// ---------------------------------------------------------------------------
__global__ void __launch_bounds__(256) finalize_kernel(
    const float* __restrict__ centers,
    float* __restrict__ out)
{
    const int i = blockIdx.x * blockDim.x + threadIdx.x;   // float4 index
    const int c = i >> 7;                                   // 128 float4s/row
    const int lane = threadIdx.x & 31;
    const int wid  = threadIdx.x >> 5;

    const int cnt = g_hist[c];

    float4* __restrict__ sp = reinterpret_cast<float4*>(g_sums) + i;
    const float4 sv = *sp;
    const float4 cv = reinterpret_cast<const float4*>(centers)[i];
    const float fcnt = (float)cnt;

    float lp = fcnt * (cv.x*cv.x + cv.y*cv.y + cv.z*cv.z + cv.w*cv.w)
             - 2.0f * (cv.x*sv.x + cv.y*sv.y + cv.z*sv.z + cv.w*sv.w);

    float ox, oy, oz, ow;
    if (cnt > 0) {
        const float inv = 0.5f / fcnt;        // ALPHA = 0.5
        ox = 0.5f * cv.x + sv.x * inv;
        oy = 0.5f * cv.y + sv.y * inv;
        oz = 0.5f * cv.z + sv.z * inv;
        ow = 0.5f * cv.w + sv.w * inv;
    } else {
        ox = cv.x; oy = cv.y; oz = cv.z; ow = cv.w;
    }
    float* o = out + 1 + (size_t)i * 4;       // out[0] is the loss scalar
    o[0] = ox; o[1] = oy; o[2] = oz; o[3] = ow;

    *sp = make_float4(0.f, 0.f, 0.f, 0.f);    // self-reset scratch

    #pragma unroll
    for (int off = 16; off > 0; off >>= 1)
        lp += __shfl_xor_sync(0xffffffffu, lp, off);

    __shared__ float s_ws[8];
    if (lane == 0) s_ws[wid] = lp;
    __syncthreads();
    if (threadIdx.x == 0) {
        float bs = 0.0f;
        #pragma unroll
        for (int w = 0; w < 8; w++) bs += s_ws[w];
        atomicAdd(&g_loss, bs);
    }
}

// ---------------------------------------------------------------------------
// 6) Tail: loss scalar; reset g_hist / g_loss for the next call.
// ---------------------------------------------------------------------------
__global__ void __launch_bounds__(1024) tail_kernel(float* __restrict__ out)
{
    const int t = threadIdx.x;
    if (t < NUM_CLASSES) g_hist[t] = 0;
    if (t == 0) {
        out[0] = 0.5f * g_loss / (float)BATCH;
        g_loss = 0.0f;
    }
}

extern "C" void kernel_launch(void* const* d_in, const int* in_sizes, int n_in,
                              void* d_out, int out_size)
{
    const float* features = (const float*)d_in[0];
    const int*   labels   = (const int*)d_in[1];
    const float* centers  = (const float*)d_in[2];
    float*       out      = (float*)d_out;

    (void)in_sizes; (void)n_in; (void)out_size;

    hist_kernel<<<16, 1024>>>(labels);
    scan_kernel<<<1, 1024>>>();
    scatter_kernel<<<32, 1024>>>(labels);
    // BATCH/CHUNK warps, 8 warps per 256-thread block
    center_main_kernel<<<(BATCH / CHUNK) / 8, 256>>>(features);
    finalize_kernel<<<(NUM_CLASSES * F4_PER_ROW) / 256, 256>>>(centers, out);
    tail_kernel<<<1, 1024>>>(out);
}

// round 14
// speedup vs baseline: 1.0102x; 1.0102x over previous
#include <cuda_runtime.h>
#include <cuda_bf16.h>
#include <cstdint>

#define NUM_CLASSES 1000
#define FEAT_DIM    512
#define F4_PER_ROW  (FEAT_DIM / 4)     // 128
#define BATCH       32768
#define CHUNK       4                  // sorted rows per warp
// ALPHA = 0.5

// Scratch (device globals, allocation-free). Zero at module load; restored to
// zero by the kernels themselves each call => deterministic across replays.
__device__ __align__(16) float g_sums[NUM_CLASSES * FEAT_DIM];
__device__ int   g_hist[NUM_CLASSES];
__device__ int   g_offsets[NUM_CLASSES];
__device__ int   g_cursor[NUM_CLASSES];
__device__ int   g_rowidx[BATCH];
__device__ int   g_sortedlab[BATCH];
__device__ float g_loss;

// ---------------------------------------------------------------------------
// 1) Histogram of labels (smem-aggregated, merged to global).
// ---------------------------------------------------------------------------
__global__ void __launch_bounds__(1024) hist_kernel(const int* __restrict__ labels)
{
    __shared__ int sh[NUM_CLASSES];
    for (int i = threadIdx.x; i < NUM_CLASSES; i += 1024) sh[i] = 0;
    __syncthreads();

    const int stride = gridDim.x * 1024;
    for (int r = blockIdx.x * 1024 + threadIdx.x; r < BATCH; r += stride)
        atomicAdd(&sh[labels[r]], 1);
    __syncthreads();

    for (int i = threadIdx.x; i < NUM_CLASSES; i += 1024) {
        int v = sh[i];
        if (v) atomicAdd(&g_hist[i], v);
    }
}

// ---------------------------------------------------------------------------
// 2) Exclusive prefix sum over 1000 counts (single block, Hillis-Steele).
// ---------------------------------------------------------------------------
__global__ void __launch_bounds__(1024) scan_kernel()
{
    __shared__ int sh[1024];
    const int t = threadIdx.x;
    sh[t] = (t < NUM_CLASSES) ? g_hist[t] : 0;
    __syncthreads();

    #pragma unroll
    for (int off = 1; off < 1024; off <<= 1) {
        int v = (t >= off) ? sh[t - off] : 0;
        __syncthreads();
        sh[t] += v;
        __syncthreads();
    }
    if (t < NUM_CLASSES) {
        int excl = sh[t] - g_hist[t];
        g_offsets[t] = excl;
        g_cursor[t]  = excl;
    }
}

// ---------------------------------------------------------------------------
// 3) Scatter row indices (and their labels) into class-sorted order.
// ---------------------------------------------------------------------------
__global__ void __launch_bounds__(1024) scatter_kernel(const int* __restrict__ labels)
{
    const int stride = gridDim.x * 1024;
    for (int r = blockIdx.x * 1024 + threadIdx.x; r < BATCH; r += stride) {
        const int lab = labels[r];
        int pos = atomicAdd(&g_cursor[lab], 1);
        g_rowidx[pos] = r;
        g_sortedlab[pos] = lab;
    }
}

// ---------------------------------------------------------------------------
// 4) Main: one warp per CHUNK consecutive rows of the SORTED order.
//    Rows in a chunk almost always share a class -> accumulate in registers,
//    REDG-flush once per distinct label (~1.1x per chunk instead of 4x).
//    Also accumulates sum(f^2) for the loss expansion:
//      sum ||f - c[lab]||^2 = sum f^2 - 2 sum_c <s_c,c_c> + sum_c cnt_c ||c_c||^2
// ---------------------------------------------------------------------------
__device__ __forceinline__ void flush_acc(float4* acc, int lab, int lane)
{
    float* s = g_sums + (size_t)lab * FEAT_DIM;
    #pragma unroll
    for (int i = 0; i < 4; i++) {
        const int idx = lane + i * 32;
        asm volatile("red.global.add.v4.f32 [%0], {%1, %2, %3, %4};"
                     :: "l"(s + idx * 4),
                        "f"(acc[i].x), "f"(acc[i].y), "f"(acc[i].z), "f"(acc[i].w)
                     : "memory");
    }
}

__global__ void __launch_bounds__(256) center_main_kernel(
    const float* __restrict__ features)
{
    const int tid  = blockIdx.x * blockDim.x + threadIdx.x;
    const int warp = tid >> 5;          // 0 .. BATCH/CHUNK-1 (grid sized exactly)
    const int lane = threadIdx.x & 31;
    const int base = warp * CHUNK;

    const float4* __restrict__ F = reinterpret_cast<const float4*>(features);

    // chunk metadata (uniform loads -> broadcast)
    int rows[CHUNK], labs[CHUNK];
    #pragma unroll
    for (int j = 0; j < CHUNK; j++) {
        rows[j] = g_rowidx[base + j];
        labs[j] = g_sortedlab[base + j];
    }

    float sumsq = 0.0f;
    float4 acc[4];
    int cur = labs[0];

    // row 0 initializes the accumulator
    {
        const size_t ro = (size_t)rows[0] * F4_PER_ROW;
        #pragma unroll
        for (int i = 0; i < 4; i++) {
            float4 v = F[ro + lane + i * 32];
            acc[i] = v;
            sumsq += v.x * v.x + v.y * v.y + v.z * v.z + v.w * v.w;
        }
    }

    #pragma unroll
    for (int j = 1; j < CHUNK; j++) {
        const size_t ro = (size_t)rows[j] * F4_PER_ROW;
        float4 v[4];
        #pragma unroll
        for (int i = 0; i < 4; i++) v[i] = F[ro + lane + i * 32];

        if (labs[j] != cur) {               // rare (~12% of chunks)
            flush_acc(acc, cur, lane);
            cur = labs[j];
            #pragma unroll
            for (int i = 0; i < 4; i++) acc[i] = v[i];
        } else {
            #pragma unroll
            for (int i = 0; i < 4; i++) {
                acc[i].x += v[i].x; acc[i].y += v[i].y;
                acc[i].z += v[i].z; acc[i].w += v[i].w;
            }
        }
        #pragma unroll
        for (int i = 0; i < 4; i++)
            sumsq += v[i].x * v[i].x + v[i].y * v[i].y
                   + v[i].z * v[i].z + v[i].w * v[i].w;
    }
    flush_acc(acc, cur, lane);

    // ---- block-reduce sum(f^2) -> one atomic per block ----
    #pragma unroll
    for (int off = 16; off > 0; off >>= 1)
        sumsq += __shfl_xor_sync(0xffffffffu, sumsq, off);

    __shared__ float s_ws[8];
    const int wib = threadIdx.x >> 5;
    if (lane == 0) s_ws[wib] = sumsq;
    __syncthreads();
    if (threadIdx.x == 0) {
        float bs = 0.0f;
        #pragma unroll
        for (int w = 0; w < 8; w++) bs += s_ws[w];
        atomicAdd(&g_loss, bs);
    }
}

// ---------------------------------------------------------------------------
// 5) Finalize: flat, one float4 element per thread (128000 threads).
//    Center update + loss cross/quadratic terms + g_sums self-reset.
// ---------------------------------------------------------------------------
__global__ void __launch_bounds__(256) finalize_kernel(
    const float* __restrict__ centers,
    float* __restrict__ out)
{
    const int i = blockIdx.x * blockDim.x + threadIdx.x;   // float4 index
    const int c = i >> 7;                                   // 128 float4s/row
    const int lane = threadIdx.x & 31;
    const int wid  = threadIdx.x >> 5;

    const int cnt = g_hist[c];

    float4* __restrict__ sp = reinterpret_cast<float4*>(g_sums) + i;
    const float4 sv = *sp;
    const float4 cv = reinterpret_cast<const float4*>(centers)[i];
    const float fcnt = (float)cnt;

    float lp = fcnt * (cv.x*cv.x + cv.y*cv.y + cv.z*cv.z + cv.w*cv.w)
             - 2.0f * (cv.x*sv.x + cv.y*sv.y + cv.z*sv.z + cv.w*sv.w);

    float ox, oy, oz, ow;
    if (cnt > 0) {
        const float inv = 0.5f / fcnt;        // ALPHA = 0.5
        ox = 0.5f * cv.x + sv.x * inv;
        oy = 0.5f * cv.y + sv.y * inv;
        oz = 0.5f * cv.z + sv.z * inv;
        ow = 0.5f * cv.w + sv.w * inv;
    } else {
        ox = cv.x; oy = cv.y; oz = cv.z; ow = cv.w;
    }
    float* o = out + 1 + (size_t)i * 4;       // out[0] is the loss scalar
    o[0] = ox; o[1] = oy; o[2] = oz; o[3] = ow;

    *sp = make_float4(0.f, 0.f, 0.f, 0.f);    // self-reset scratch

    #pragma unroll
    for (int off = 16; off > 0; off >>= 1)
        lp += __shfl_xor_sync(0xffffffffu, lp, off);

    __shared__ float s_ws[8];
    if (lane == 0) s_ws[wid] = lp;
    __syncthreads();
    if (threadIdx.x == 0) {
        float bs = 0.0f;
        #pragma unroll
        for (int w = 0; w < 8; w++) bs += s_ws[w];
        atomicAdd(&g_loss, bs);
    }
}

// ---------------------------------------------------------------------------
// 6) Tail: loss scalar; reset g_hist / g_loss for the next call.
// ---------------------------------------------------------------------------
__global__ void __launch_bounds__(1024) tail_kernel(float* __restrict__ out)
{
    const int t = threadIdx.x;
    if (t < NUM_CLASSES) g_hist[t] = 0;
    if (t == 0) {
        out[0] = 0.5f * g_loss / (float)BATCH;
        g_loss = 0.0f;
    }
}

extern "C" void kernel_launch(void* const* d_in, const int* in_sizes, int n_in,
                              void* d_out, int out_size)
{
    const float* features = (const float*)d_in[0];
    const int*   labels   = (const int*)d_in[1];
    const float* centers  = (const float*)d_in[2];
    float*       out      = (float*)d_out;

    (void)in_sizes; (void)n_in; (void)out_size;

    hist_kernel<<<16, 1024>>>(labels);
    scan_kernel<<<1, 1024>>>();
    scatter_kernel<<<32, 1024>>>(labels);
    // BATCH/CHUNK warps, 8 warps per 256-thread block
    center_main_kernel<<<(BATCH / CHUNK) / 8, 256>>>(features);
    finalize_kernel<<<(NUM_CLASSES * F4_PER_ROW) / 256, 256>>>(centers, out);
    tail_kernel<<<1, 1024>>>(out);
}